// round 7
// baseline (speedup 1.0000x reference)
#include <cuda_runtime.h>
#include <cuda_bf16.h>

// Problem constants (fixed shapes per reference)
#define MAXN 50000
#define MAXE 800000
#define DOUT 128

// ---------------- device scratch (no allocation allowed) ----------------
__device__ float g_xw[(size_t)MAXN * DOUT];     // 25.6 MB
__device__ float g_asrc[MAXN];
__device__ float g_adst[MAXN];
__device__ int   g_deg[MAXN];
__device__ int   g_off[MAXN + 1];
__device__ int   g_cursor[MAXN];
__device__ int   g_ssrc[MAXE + MAXN];           // sorted-by-dst source indices

// ---------------- kernels ----------------

__global__ void zero_deg_kernel(int n) {
    int i = blockIdx.x * blockDim.x + threadIdx.x;
    if (i < n) g_deg[i] = 0;
}

// GEMM: xw = x @ W.  Block = 128 threads, 32 rows per block.
// Thread c owns output column c. W staged in 32-row k-chunks (16KB smem),
// x tile staged once (16KB). W column chunk cached in 32 regs per thread.
__global__ __launch_bounds__(128) void gemm_kernel(
    const float* __restrict__ x, const float* __restrict__ W, int n)
{
    __shared__ float Ws[32 * 128];   // 16 KB, chunk of W rows
    __shared__ float Xs[32 * 128];   // 16 KB, x tile
    const int c = threadIdx.x;
    const int row0 = blockIdx.x * 32;
    const int nrows = min(32, n - row0);

    // load x tile (vectorized), zero-fill tail rows
    const float4* x4 = (const float4*)(x + (size_t)row0 * 128);
    float4* Xs4 = (float4*)Xs;
    for (int i = c; i < 32 * 32; i += 128)
        Xs4[i] = (i < nrows * 32) ? x4[i] : make_float4(0.f, 0.f, 0.f, 0.f);

    float acc[32];
#pragma unroll
    for (int r = 0; r < 32; r++) acc[r] = 0.f;

    const float4* W4 = (const float4*)W;
    float4* Ws4 = (float4*)Ws;

    for (int kb = 0; kb < 4; kb++) {
        __syncthreads();
        // stage W rows [kb*32, kb*32+32)
        for (int i = c; i < 32 * 32; i += 128)
            Ws4[i] = W4[kb * 1024 + i];
        __syncthreads();
        // cache this thread's W column chunk in registers
        float wreg[32];
#pragma unroll
        for (int j = 0; j < 32; j++) wreg[j] = Ws[j * 128 + c];
#pragma unroll 4
        for (int r = 0; r < 32; r++) {
            const float4* xr = (const float4*)(Xs + r * 128 + kb * 32);
            float a = acc[r];
#pragma unroll
            for (int j = 0; j < 8; j++) {
                float4 v = xr[j];
                a += v.x * wreg[4 * j + 0];
                a += v.y * wreg[4 * j + 1];
                a += v.z * wreg[4 * j + 2];
                a += v.w * wreg[4 * j + 3];
            }
            acc[r] = a;
        }
    }

    for (int r = 0; r < nrows; r++)
        g_xw[(size_t)(row0 + r) * 128 + c] = acc[r];
}

// Per-node attention logits: asrc[i] = xw[i]·att_src, adst[i] = xw[i]·att_dst.
// One warp per row.
__global__ void attdot_kernel(const float* __restrict__ att_src,
                              const float* __restrict__ att_dst, int n)
{
    int gt = blockIdx.x * blockDim.x + threadIdx.x;
    int row = gt >> 5;
    int lane = gt & 31;
    if (row >= n) return;
    float4 v  = ((const float4*)(g_xw + (size_t)row * 128))[lane];
    float4 as = ((const float4*)att_src)[lane];
    float4 ad = ((const float4*)att_dst)[lane];
    float s = v.x * as.x + v.y * as.y + v.z * as.z + v.w * as.w;
    float d = v.x * ad.x + v.y * ad.y + v.z * ad.z + v.w * ad.w;
#pragma unroll
    for (int o = 16; o; o >>= 1) {
        s += __shfl_xor_sync(0xFFFFFFFFu, s, o);
        d += __shfl_xor_sync(0xFFFFFFFFu, d, o);
    }
    if (lane == 0) { g_asrc[row] = s; g_adst[row] = d; }
}

// Degree histogram over dst, including the N self-loops (i >= E).
// edge_index is int32 (JAX default config downcasts int64 -> int32).
__global__ void hist_kernel(const int* __restrict__ ei, int E, int n)
{
    int i = blockIdx.x * blockDim.x + threadIdx.x;
    if (i >= E + n) return;
    int d = (i < E) ? ei[E + i] : (i - E);
    atomicAdd(&g_deg[d], 1);
}

// Exclusive scan of deg -> off (and cursor copy). Single block, 1024 threads,
// chunked Hillis-Steele with carry. n = 50000 -> 49 chunks, a few microseconds.
__global__ __launch_bounds__(1024) void scan_kernel(int n)
{
    __shared__ int sm[1024];
    __shared__ int carry_s;
    int t = threadIdx.x;
    if (t == 0) carry_s = 0;
    __syncthreads();
    for (int base = 0; base < n; base += 1024) {
        int i = base + t;
        int v = (i < n) ? g_deg[i] : 0;
        sm[t] = v;
        __syncthreads();
#pragma unroll
        for (int o = 1; o < 1024; o <<= 1) {
            int add = (t >= o) ? sm[t - o] : 0;
            __syncthreads();
            sm[t] += add;
            __syncthreads();
        }
        int carry = carry_s;
        if (i < n) {
            int excl = carry + sm[t] - v;
            g_off[i] = excl;
            g_cursor[i] = excl;
        }
        __syncthreads();
        if (t == 0) carry_s = carry + sm[1023];
        __syncthreads();
    }
    if (t == 0) g_off[n] = carry_s;
}

// Scatter source indices into dst-sorted order via atomic cursors.
__global__ void scatter_kernel(const int* __restrict__ ei, int E, int n)
{
    int i = blockIdx.x * blockDim.x + threadIdx.x;
    if (i >= E + n) return;
    int s, d;
    if (i < E) { s = ei[i]; d = ei[E + i]; }
    else       { s = d = i - E; }
    int p = atomicAdd(&g_cursor[d], 1);
    g_ssrc[p] = s;
}

// Aggregate: one warp per destination node. Softmax over segment, then
// weighted gather of xw rows. Lane l owns feature columns [4l, 4l+4).
__global__ __launch_bounds__(256) void agg_kernel(
    const float* __restrict__ bias, float* __restrict__ out, int n)
{
    int gt = blockIdx.x * blockDim.x + threadIdx.x;
    int node = gt >> 5;
    int lane = gt & 31;
    if (node >= n) return;

    int b = g_off[node], e = g_off[node + 1];
    float adst_d = g_adst[node];

    // pass 1: segment max of leaky_relu logits
    float m = -1e30f;
    for (int i = b + lane; i < e; i += 32) {
        float t = g_asrc[g_ssrc[i]] + adst_d;
        t = (t > 0.f) ? t : 0.2f * t;
        m = fmaxf(m, t);
    }
#pragma unroll
    for (int o = 16; o; o >>= 1) m = fmaxf(m, __shfl_xor_sync(0xFFFFFFFFu, m, o));

    // pass 2: denom
    float sum = 0.f;
    for (int i = b + lane; i < e; i += 32) {
        float t = g_asrc[g_ssrc[i]] + adst_d;
        t = (t > 0.f) ? t : 0.2f * t;
        sum += __expf(t - m);
    }
#pragma unroll
    for (int o = 16; o; o >>= 1) sum += __shfl_xor_sync(0xFFFFFFFFu, sum, o);
    float rden = 1.f / sum;

    // pass 3: weighted gather, 2-way unrolled so two independent
    // index->logit->row load chains are in flight (MLP~2 vs ~1).
    float4 acc0 = make_float4(0.f, 0.f, 0.f, 0.f);
    float4 acc1 = make_float4(0.f, 0.f, 0.f, 0.f);
    int i = b;
    for (; i + 1 < e; i += 2) {
        int s0 = g_ssrc[i];
        int s1 = g_ssrc[i + 1];
        float t0 = g_asrc[s0] + adst_d;
        float t1 = g_asrc[s1] + adst_d;
        const float4* p0 = (const float4*)(g_xw + (size_t)s0 * 128) + lane;
        const float4* p1 = (const float4*)(g_xw + (size_t)s1 * 128) + lane;
        float4 v0 = *p0;
        float4 v1 = *p1;
        t0 = (t0 > 0.f) ? t0 : 0.2f * t0;
        t1 = (t1 > 0.f) ? t1 : 0.2f * t1;
        float a0 = __expf(t0 - m) * rden;
        float a1 = __expf(t1 - m) * rden;
        acc0.x += a0 * v0.x; acc0.y += a0 * v0.y;
        acc0.z += a0 * v0.z; acc0.w += a0 * v0.w;
        acc1.x += a1 * v1.x; acc1.y += a1 * v1.y;
        acc1.z += a1 * v1.z; acc1.w += a1 * v1.w;
    }
    if (i < e) {
        int s0 = g_ssrc[i];
        float t0 = g_asrc[s0] + adst_d;
        t0 = (t0 > 0.f) ? t0 : 0.2f * t0;
        float a0 = __expf(t0 - m) * rden;
        float4 v0 = *((const float4*)(g_xw + (size_t)s0 * 128) + lane);
        acc0.x += a0 * v0.x; acc0.y += a0 * v0.y;
        acc0.z += a0 * v0.z; acc0.w += a0 * v0.w;
    }
    float4 acc = make_float4(acc0.x + acc1.x, acc0.y + acc1.y,
                             acc0.z + acc1.z, acc0.w + acc1.w);

    float4 bb = ((const float4*)bias)[lane];
    acc.x += bb.x; acc.y += bb.y; acc.z += bb.z; acc.w += bb.w;
    // ELU
    acc.x = (acc.x > 0.f) ? acc.x : (__expf(acc.x) - 1.f);
    acc.y = (acc.y > 0.f) ? acc.y : (__expf(acc.y) - 1.f);
    acc.z = (acc.z > 0.f) ? acc.z : (__expf(acc.z) - 1.f);
    acc.w = (acc.w > 0.f) ? acc.w : (__expf(acc.w) - 1.f);

    *(float4*)(out + (size_t)node * 128 + lane * 4) = acc;
}

// ---------------- launch ----------------

extern "C" void kernel_launch(void* const* d_in, const int* in_sizes, int n_in,
                              void* d_out, int out_size)
{
    const float* x    = (const float*)d_in[0];
    const int*   ei   = (const int*)d_in[1];   // int32! (JAX default: no x64)
    const float* W    = (const float*)d_in[2];
    const float* asv  = (const float*)d_in[3];
    const float* adv  = (const float*)d_in[4];
    const float* bias = (const float*)d_in[5];
    float* out = (float*)d_out;

    const int n = in_sizes[0] / DOUT;       // 50000
    const int E = in_sizes[1] / 2;          // 800000
    const int tot = E + n;

    zero_deg_kernel<<<(n + 255) / 256, 256>>>(n);
    gemm_kernel<<<(n + 31) / 32, 128>>>(x, W, n);
    attdot_kernel<<<(n * 32 + 255) / 256, 256>>>(asv, adv, n);
    hist_kernel<<<(tot + 255) / 256, 256>>>(ei, E, n);
    scan_kernel<<<1, 1024>>>(n);
    scatter_kernel<<<(tot + 255) / 256, 256>>>(ei, E, n);
    agg_kernel<<<(n + 7) / 8, 256>>>(bias, out, n);
}

// round 9
// speedup vs baseline: 1.4109x; 1.4109x over previous
#include <cuda_runtime.h>
#include <cuda_bf16.h>

// Problem constants (fixed shapes per reference)
#define MAXN 50000
#define MAXE 800000
#define DOUT 128

// ---------------- device scratch (no allocation allowed) ----------------
__device__ float g_xw[(size_t)MAXN * DOUT];     // 25.6 MB
__device__ float g_asrc[MAXN];
__device__ float g_adst[MAXN];
__device__ int   g_deg[MAXN];
__device__ int   g_off[MAXN + 1];
__device__ int   g_cursor[MAXN];
__device__ int   g_bsum[64];                    // per-block sums for scan
__device__ int   g_ssrc[MAXE + MAXN];           // sorted-by-dst source indices

// ---------------- kernels ----------------

__global__ void zero_deg_kernel(int n) {
    int i = blockIdx.x * blockDim.x + threadIdx.x;
    if (i < n) g_deg[i] = 0;
}

// GEMM: xw = x @ W.  Block = 128 threads, 32 rows per block.
__global__ __launch_bounds__(128) void gemm_kernel(
    const float* __restrict__ x, const float* __restrict__ W, int n)
{
    __shared__ float Ws[32 * 128];   // 16 KB, chunk of W rows
    __shared__ float Xs[32 * 128];   // 16 KB, x tile
    const int c = threadIdx.x;
    const int row0 = blockIdx.x * 32;
    const int nrows = min(32, n - row0);

    const float4* x4 = (const float4*)(x + (size_t)row0 * 128);
    float4* Xs4 = (float4*)Xs;
    for (int i = c; i < 32 * 32; i += 128)
        Xs4[i] = (i < nrows * 32) ? x4[i] : make_float4(0.f, 0.f, 0.f, 0.f);

    float acc[32];
#pragma unroll
    for (int r = 0; r < 32; r++) acc[r] = 0.f;

    const float4* W4 = (const float4*)W;
    float4* Ws4 = (float4*)Ws;

    for (int kb = 0; kb < 4; kb++) {
        __syncthreads();
        for (int i = c; i < 32 * 32; i += 128)
            Ws4[i] = W4[kb * 1024 + i];
        __syncthreads();
        float wreg[32];
#pragma unroll
        for (int j = 0; j < 32; j++) wreg[j] = Ws[j * 128 + c];
#pragma unroll 4
        for (int r = 0; r < 32; r++) {
            const float4* xr = (const float4*)(Xs + r * 128 + kb * 32);
            float a = acc[r];
#pragma unroll
            for (int j = 0; j < 8; j++) {
                float4 v = xr[j];
                a += v.x * wreg[4 * j + 0];
                a += v.y * wreg[4 * j + 1];
                a += v.z * wreg[4 * j + 2];
                a += v.w * wreg[4 * j + 3];
            }
            acc[r] = a;
        }
    }

    for (int r = 0; r < nrows; r++)
        g_xw[(size_t)(row0 + r) * 128 + c] = acc[r];
}

// Per-node attention logits. One warp per row.
__global__ void attdot_kernel(const float* __restrict__ att_src,
                              const float* __restrict__ att_dst, int n)
{
    int gt = blockIdx.x * blockDim.x + threadIdx.x;
    int row = gt >> 5;
    int lane = gt & 31;
    if (row >= n) return;
    float4 v  = ((const float4*)(g_xw + (size_t)row * 128))[lane];
    float4 as = ((const float4*)att_src)[lane];
    float4 ad = ((const float4*)att_dst)[lane];
    float s = v.x * as.x + v.y * as.y + v.z * as.z + v.w * as.w;
    float d = v.x * ad.x + v.y * ad.y + v.z * ad.z + v.w * ad.w;
#pragma unroll
    for (int o = 16; o; o >>= 1) {
        s += __shfl_xor_sync(0xFFFFFFFFu, s, o);
        d += __shfl_xor_sync(0xFFFFFFFFu, d, o);
    }
    if (lane == 0) { g_asrc[row] = s; g_adst[row] = d; }
}

// Degree histogram over dst, including the N self-loops (i >= E).
__global__ void hist_kernel(const int* __restrict__ ei, int E, int n)
{
    int i = blockIdx.x * blockDim.x + threadIdx.x;
    if (i >= E + n) return;
    int d = (i < E) ? ei[E + i] : (i - E);
    atomicAdd(&g_deg[d], 1);
}

// ---- parallel 3-stage exclusive scan of g_deg -> g_off/g_cursor ----
// Stage 1: per-block (1024 elems) warp-shuffle scan; partial exclusive
// scan to g_off, block total to g_bsum.
__global__ __launch_bounds__(1024) void scan1_kernel(int n)
{
    __shared__ int wsum[32];
    int i = blockIdx.x * 1024 + threadIdx.x;
    int lane = threadIdx.x & 31;
    int w = threadIdx.x >> 5;
    int v = (i < n) ? g_deg[i] : 0;
    int inc = v;
#pragma unroll
    for (int o = 1; o < 32; o <<= 1) {
        int t = __shfl_up_sync(0xFFFFFFFFu, inc, o);
        if (lane >= o) inc += t;
    }
    if (lane == 31) wsum[w] = inc;
    __syncthreads();
    if (w == 0) {
        int s = wsum[lane];
#pragma unroll
        for (int o = 1; o < 32; o <<= 1) {
            int t = __shfl_up_sync(0xFFFFFFFFu, s, o);
            if (lane >= o) s += t;
        }
        wsum[lane] = s;
    }
    __syncthreads();
    int woff = (w == 0) ? 0 : wsum[w - 1];
    if (i < n) g_off[i] = woff + inc - v;       // block-local exclusive
    if (threadIdx.x == 1023) g_bsum[blockIdx.x] = wsum[31];
}

// Stage 2: one warp scans the (<=64) block sums into exclusive offsets,
// and writes the grand total to g_off[n].
__global__ void scan2_kernel(int nb, int n)
{
    int lane = threadIdx.x;   // 32 threads
    int carry = 0;
    for (int base = 0; base < nb; base += 32) {
        int idx = base + lane;
        int v = (idx < nb) ? g_bsum[idx] : 0;
        int inc = v;
#pragma unroll
        for (int o = 1; o < 32; o <<= 1) {
            int t = __shfl_up_sync(0xFFFFFFFFu, inc, o);
            if (lane >= o) inc += t;
        }
        if (idx < nb) g_bsum[idx] = carry + inc - v;   // exclusive
        carry += __shfl_sync(0xFFFFFFFFu, inc, 31);
    }
    if (lane == 0) g_off[n] = carry;
}

// Stage 3: add block offsets; materialize g_off and g_cursor.
__global__ __launch_bounds__(1024) void scan3_kernel(int n)
{
    int i = blockIdx.x * 1024 + threadIdx.x;
    if (i < n) {
        int off = g_off[i] + g_bsum[blockIdx.x];
        g_off[i] = off;
        g_cursor[i] = off;
    }
}

// Scatter source indices into dst-sorted order via atomic cursors.
__global__ void scatter_kernel(const int* __restrict__ ei, int E, int n)
{
    int i = blockIdx.x * blockDim.x + threadIdx.x;
    if (i >= E + n) return;
    int s, d;
    if (i < E) { s = ei[i]; d = ei[E + i]; }
    else       { s = d = i - E; }
    int p = atomicAdd(&g_cursor[d], 1);
    g_ssrc[p] = s;
}

// Aggregate: one warp per destination node.
__global__ __launch_bounds__(256) void agg_kernel(
    const float* __restrict__ bias, float* __restrict__ out, int n)
{
    int gt = blockIdx.x * blockDim.x + threadIdx.x;
    int node = gt >> 5;
    int lane = gt & 31;
    if (node >= n) return;

    int b = g_off[node], e = g_off[node + 1];
    float adst_d = g_adst[node];

    // pass 1: segment max of leaky_relu logits
    float m = -1e30f;
    for (int i = b + lane; i < e; i += 32) {
        float t = g_asrc[g_ssrc[i]] + adst_d;
        t = (t > 0.f) ? t : 0.2f * t;
        m = fmaxf(m, t);
    }
#pragma unroll
    for (int o = 16; o; o >>= 1) m = fmaxf(m, __shfl_xor_sync(0xFFFFFFFFu, m, o));

    // pass 2: denom
    float sum = 0.f;
    for (int i = b + lane; i < e; i += 32) {
        float t = g_asrc[g_ssrc[i]] + adst_d;
        t = (t > 0.f) ? t : 0.2f * t;
        sum += __expf(t - m);
    }
#pragma unroll
    for (int o = 16; o; o >>= 1) sum += __shfl_xor_sync(0xFFFFFFFFu, sum, o);
    float rden = 1.f / sum;

    // pass 3: weighted gather, 2-way unrolled (MLP~2)
    float4 acc0 = make_float4(0.f, 0.f, 0.f, 0.f);
    float4 acc1 = make_float4(0.f, 0.f, 0.f, 0.f);
    int i = b;
    for (; i + 1 < e; i += 2) {
        int s0 = g_ssrc[i];
        int s1 = g_ssrc[i + 1];
        float t0 = g_asrc[s0] + adst_d;
        float t1 = g_asrc[s1] + adst_d;
        const float4* p0 = (const float4*)(g_xw + (size_t)s0 * 128) + lane;
        const float4* p1 = (const float4*)(g_xw + (size_t)s1 * 128) + lane;
        float4 v0 = *p0;
        float4 v1 = *p1;
        t0 = (t0 > 0.f) ? t0 : 0.2f * t0;
        t1 = (t1 > 0.f) ? t1 : 0.2f * t1;
        float a0 = __expf(t0 - m) * rden;
        float a1 = __expf(t1 - m) * rden;
        acc0.x += a0 * v0.x; acc0.y += a0 * v0.y;
        acc0.z += a0 * v0.z; acc0.w += a0 * v0.w;
        acc1.x += a1 * v1.x; acc1.y += a1 * v1.y;
        acc1.z += a1 * v1.z; acc1.w += a1 * v1.w;
    }
    if (i < e) {
        int s0 = g_ssrc[i];
        float t0 = g_asrc[s0] + adst_d;
        t0 = (t0 > 0.f) ? t0 : 0.2f * t0;
        float a0 = __expf(t0 - m) * rden;
        float4 v0 = *((const float4*)(g_xw + (size_t)s0 * 128) + lane);
        acc0.x += a0 * v0.x; acc0.y += a0 * v0.y;
        acc0.z += a0 * v0.z; acc0.w += a0 * v0.w;
    }
    float4 acc = make_float4(acc0.x + acc1.x, acc0.y + acc1.y,
                             acc0.z + acc1.z, acc0.w + acc1.w);

    float4 bb = ((const float4*)bias)[lane];
    acc.x += bb.x; acc.y += bb.y; acc.z += bb.z; acc.w += bb.w;
    // ELU
    acc.x = (acc.x > 0.f) ? acc.x : (__expf(acc.x) - 1.f);
    acc.y = (acc.y > 0.f) ? acc.y : (__expf(acc.y) - 1.f);
    acc.z = (acc.z > 0.f) ? acc.z : (__expf(acc.z) - 1.f);
    acc.w = (acc.w > 0.f) ? acc.w : (__expf(acc.w) - 1.f);

    *(float4*)(out + (size_t)node * 128 + lane * 4) = acc;
}

// ---------------- launch ----------------

extern "C" void kernel_launch(void* const* d_in, const int* in_sizes, int n_in,
                              void* d_out, int out_size)
{
    const float* x    = (const float*)d_in[0];
    const int*   ei   = (const int*)d_in[1];   // int32 (JAX default: no x64)
    const float* W    = (const float*)d_in[2];
    const float* asv  = (const float*)d_in[3];
    const float* adv  = (const float*)d_in[4];
    const float* bias = (const float*)d_in[5];
    float* out = (float*)d_out;

    const int n = in_sizes[0] / DOUT;       // 50000
    const int E = in_sizes[1] / 2;          // 800000
    const int tot = E + n;
    const int nb = (n + 1023) / 1024;       // 49 scan blocks

    zero_deg_kernel<<<(n + 255) / 256, 256>>>(n);
    gemm_kernel<<<(n + 31) / 32, 128>>>(x, W, n);
    attdot_kernel<<<(n * 32 + 255) / 256, 256>>>(asv, adv, n);
    hist_kernel<<<(tot + 255) / 256, 256>>>(ei, E, n);
    scan1_kernel<<<nb, 1024>>>(n);
    scan2_kernel<<<1, 32>>>(nb, n);
    scan3_kernel<<<nb, 1024>>>(n);
    scatter_kernel<<<(tot + 255) / 256, 256>>>(ei, E, n);
    agg_kernel<<<(n + 7) / 8, 256>>>(bias, out, n);
}